// round 1
// baseline (speedup 1.0000x reference)
#include <cuda_runtime.h>
#include <math.h>

#define BB   512
#define TT   1024
#define DIN  128
#define HH   512
#define DOUT 128
#define MB   4
#define NCTA (BB / MB)   // 128
#define NTHR 512

// Scratch: weights re-laid-out as [k/4][j][4] so thread j streams float4
// over K with perfectly coalesced LDG.128 (lanes consecutive j -> 16B stride).
__device__ float g_Wh4[HH * HH];    // 1 MB
__device__ float g_Wx4[DIN * HH];   // 256 KB

__global__ void prep_kernel(const float* __restrict__ Wh,
                            const float* __restrict__ Wx) {
    int i = blockIdx.x * blockDim.x + threadIdx.x;
    int stride = gridDim.x * blockDim.x;
    for (int idx = i; idx < HH * HH; idx += stride) {
        int j = idx / HH;
        int k = idx % HH;
        g_Wh4[(k >> 2) * (HH * 4) + j * 4 + (k & 3)] = Wh[idx];
    }
    for (int idx = i; idx < HH * DIN; idx += stride) {
        int j = idx / DIN;
        int d = idx % DIN;
        g_Wx4[(d >> 2) * (HH * 4) + j * 4 + (d & 3)] = Wx[idx];
    }
}

__global__ __launch_bounds__(NTHR, 1) void scan_kernel(
    const float* __restrict__ x,
    const float* __restrict__ bx,
    const float* __restrict__ bh,
    const float* __restrict__ Wy,
    const float* __restrict__ by,
    float* __restrict__ y)
{
    // h_s[buf][k] : float4 components are the MB=4 batch rows (layout [k][m])
    __shared__ float4 h_s[2][HH];   // 2 x 8 KB
    __shared__ float4 x_s[DIN];     // 2 KB, layout [d][m]

    const int tid = threadIdx.x;
    const int j   = tid;            // this thread owns hidden unit j
    const int b0  = blockIdx.x * MB;

    const float bias = bx[j] + bh[j];

    const float4* __restrict__ Wh4 = reinterpret_cast<const float4*>(g_Wh4);
    const float4* __restrict__ Wx4 = reinterpret_cast<const float4*>(g_Wx4);

    // h_0 = 0
    h_s[0][tid] = make_float4(0.f, 0.f, 0.f, 0.f);

    const int xd = tid >> 2;        // d index for x staging
    const int xm = tid & 3;         // m index for x staging
    const long xbase = ((long)(b0 + xm) * TT) * DIN + xd;

    int cur = 0;
    for (int t = 0; t < TT; ++t) {
        // stage x[b0+m][t][:]  (x_s flat index d*4+m == tid)
        reinterpret_cast<float*>(x_s)[tid] = x[xbase + (long)t * DIN];
        __syncthreads();   // x_s ready; h_s[cur] ready from previous step

        float a0 = bias, a1 = bias, a2 = bias, a3 = bias;

        // input projection: a_m += sum_d Wx[j][d] * x[m][d]
        #pragma unroll 4
        for (int d4 = 0; d4 < DIN / 4; ++d4) {
            float4 w  = Wx4[d4 * HH + j];
            float4 p0 = x_s[d4 * 4 + 0];
            float4 p1 = x_s[d4 * 4 + 1];
            float4 p2 = x_s[d4 * 4 + 2];
            float4 p3 = x_s[d4 * 4 + 3];
            a0 = fmaf(w.x, p0.x, a0); a0 = fmaf(w.y, p1.x, a0);
            a0 = fmaf(w.z, p2.x, a0); a0 = fmaf(w.w, p3.x, a0);
            a1 = fmaf(w.x, p0.y, a1); a1 = fmaf(w.y, p1.y, a1);
            a1 = fmaf(w.z, p2.y, a1); a1 = fmaf(w.w, p3.y, a1);
            a2 = fmaf(w.x, p0.z, a2); a2 = fmaf(w.y, p1.z, a2);
            a2 = fmaf(w.z, p2.z, a2); a2 = fmaf(w.w, p3.z, a2);
            a3 = fmaf(w.x, p0.w, a3); a3 = fmaf(w.y, p1.w, a3);
            a3 = fmaf(w.z, p2.w, a3); a3 = fmaf(w.w, p3.w, a3);
        }

        // recurrence: a_m += sum_k Wh[j][k] * h[m][k]
        const float4* __restrict__ hc = h_s[cur];
        #pragma unroll 8
        for (int k4 = 0; k4 < HH / 4; ++k4) {
            float4 w  = Wh4[k4 * HH + j];
            float4 p0 = hc[k4 * 4 + 0];
            float4 p1 = hc[k4 * 4 + 1];
            float4 p2 = hc[k4 * 4 + 2];
            float4 p3 = hc[k4 * 4 + 3];
            a0 = fmaf(w.x, p0.x, a0); a0 = fmaf(w.y, p1.x, a0);
            a0 = fmaf(w.z, p2.x, a0); a0 = fmaf(w.w, p3.x, a0);
            a1 = fmaf(w.x, p0.y, a1); a1 = fmaf(w.y, p1.y, a1);
            a1 = fmaf(w.z, p2.y, a1); a1 = fmaf(w.w, p3.y, a1);
            a2 = fmaf(w.x, p0.z, a2); a2 = fmaf(w.y, p1.z, a2);
            a2 = fmaf(w.z, p2.z, a2); a2 = fmaf(w.w, p3.z, a2);
            a3 = fmaf(w.x, p0.w, a3); a3 = fmaf(w.y, p1.w, a3);
            a3 = fmaf(w.z, p2.w, a3); a3 = fmaf(w.w, p3.w, a3);
        }

        h_s[cur ^ 1][j] = make_float4(tanhf(a0), tanhf(a1), tanhf(a2), tanhf(a3));
        __syncthreads();   // writes done, x_s free to overwrite
        cur ^= 1;
    }

    // epilogue: y[b0+m][o] = by[o] + sum_k Wy[o][k] * h_T[m][k]
    const int m = tid >> 7;          // 0..3
    const int o = tid & 127;         // 0..127
    const float* __restrict__ hflat = reinterpret_cast<const float*>(h_s[cur]);
    const float4* __restrict__ Wy4  = reinterpret_cast<const float4*>(Wy);

    float acc = by[o];
    #pragma unroll 8
    for (int k4 = 0; k4 < HH / 4; ++k4) {
        float4 w = Wy4[o * (HH / 4) + k4];
        acc = fmaf(w.x, hflat[(k4 * 4 + 0) * 4 + m], acc);
        acc = fmaf(w.y, hflat[(k4 * 4 + 1) * 4 + m], acc);
        acc = fmaf(w.z, hflat[(k4 * 4 + 2) * 4 + m], acc);
        acc = fmaf(w.w, hflat[(k4 * 4 + 3) * 4 + m], acc);
    }
    y[(b0 + m) * DOUT + o] = acc;
}

extern "C" void kernel_launch(void* const* d_in, const int* in_sizes, int n_in,
                              void* d_out, int out_size) {
    const float* x  = (const float*)d_in[0];
    const float* Wx = (const float*)d_in[1];
    const float* bx = (const float*)d_in[2];
    const float* Wh = (const float*)d_in[3];
    const float* bh = (const float*)d_in[4];
    const float* Wy = (const float*)d_in[5];
    const float* by = (const float*)d_in[6];
    float* y = (float*)d_out;

    prep_kernel<<<256, 256>>>(Wh, Wx);
    scan_kernel<<<NCTA, NTHR>>>(x, bx, bh, Wy, by, y);
}

// round 2
// speedup vs baseline: 1.0004x; 1.0004x over previous
#include <cuda_runtime.h>
#include <math.h>

#define BB   512
#define TT   1024
#define DIN  128
#define HH   512
#define DOUT 128
#define MB   4
#define NCTA (BB / MB)   // 128
#define NTHR 512

// Scratch: weights re-laid-out as [k/4][j][4] so thread j streams float4
// over K with perfectly coalesced LDG.128 (lanes consecutive j -> 16B stride).
__device__ float g_Wh4[HH * HH];    // 1 MB
__device__ float g_Wx4[DIN * HH];   // 256 KB

__global__ void prep_kernel(const float* __restrict__ Wh,
                            const float* __restrict__ Wx) {
    int i = blockIdx.x * blockDim.x + threadIdx.x;
    int stride = gridDim.x * blockDim.x;
    for (int idx = i; idx < HH * HH; idx += stride) {
        int j = idx / HH;
        int k = idx % HH;
        g_Wh4[(k >> 2) * (HH * 4) + j * 4 + (k & 3)] = Wh[idx];
    }
    for (int idx = i; idx < HH * DIN; idx += stride) {
        int j = idx / DIN;
        int d = idx % DIN;
        g_Wx4[(d >> 2) * (HH * 4) + j * 4 + (d & 3)] = Wx[idx];
    }
}

__global__ __launch_bounds__(NTHR, 1) void scan_kernel(
    const float* __restrict__ x,
    const float* __restrict__ bx,
    const float* __restrict__ bh,
    const float* __restrict__ Wy,
    const float* __restrict__ by,
    float* __restrict__ y)
{
    // h_s[buf][k] : float4 components are the MB=4 batch rows (layout [k][m])
    __shared__ float4 h_s[2][HH];   // 2 x 8 KB
    __shared__ float4 x_s[DIN];     // 2 KB, layout [d][m]

    const int tid = threadIdx.x;
    const int j   = tid;            // this thread owns hidden unit j
    const int b0  = blockIdx.x * MB;

    const float bias = bx[j] + bh[j];

    const float4* __restrict__ Wh4 = reinterpret_cast<const float4*>(g_Wh4);
    const float4* __restrict__ Wx4 = reinterpret_cast<const float4*>(g_Wx4);

    // h_0 = 0
    h_s[0][tid] = make_float4(0.f, 0.f, 0.f, 0.f);

    const int xd = tid >> 2;        // d index for x staging
    const int xm = tid & 3;         // m index for x staging
    const long xbase = ((long)(b0 + xm) * TT) * DIN + xd;

    int cur = 0;
    for (int t = 0; t < TT; ++t) {
        // stage x[b0+m][t][:]  (x_s flat index d*4+m == tid)
        reinterpret_cast<float*>(x_s)[tid] = x[xbase + (long)t * DIN];
        __syncthreads();   // x_s ready; h_s[cur] ready from previous step

        float a0 = bias, a1 = bias, a2 = bias, a3 = bias;

        // input projection: a_m += sum_d Wx[j][d] * x[m][d]
        #pragma unroll 4
        for (int d4 = 0; d4 < DIN / 4; ++d4) {
            float4 w  = Wx4[d4 * HH + j];
            float4 p0 = x_s[d4 * 4 + 0];
            float4 p1 = x_s[d4 * 4 + 1];
            float4 p2 = x_s[d4 * 4 + 2];
            float4 p3 = x_s[d4 * 4 + 3];
            a0 = fmaf(w.x, p0.x, a0); a0 = fmaf(w.y, p1.x, a0);
            a0 = fmaf(w.z, p2.x, a0); a0 = fmaf(w.w, p3.x, a0);
            a1 = fmaf(w.x, p0.y, a1); a1 = fmaf(w.y, p1.y, a1);
            a1 = fmaf(w.z, p2.y, a1); a1 = fmaf(w.w, p3.y, a1);
            a2 = fmaf(w.x, p0.z, a2); a2 = fmaf(w.y, p1.z, a2);
            a2 = fmaf(w.z, p2.z, a2); a2 = fmaf(w.w, p3.z, a2);
            a3 = fmaf(w.x, p0.w, a3); a3 = fmaf(w.y, p1.w, a3);
            a3 = fmaf(w.z, p2.w, a3); a3 = fmaf(w.w, p3.w, a3);
        }

        // recurrence: a_m += sum_k Wh[j][k] * h[m][k]
        const float4* __restrict__ hc = h_s[cur];
        #pragma unroll 8
        for (int k4 = 0; k4 < HH / 4; ++k4) {
            float4 w  = Wh4[k4 * HH + j];
            float4 p0 = hc[k4 * 4 + 0];
            float4 p1 = hc[k4 * 4 + 1];
            float4 p2 = hc[k4 * 4 + 2];
            float4 p3 = hc[k4 * 4 + 3];
            a0 = fmaf(w.x, p0.x, a0); a0 = fmaf(w.y, p1.x, a0);
            a0 = fmaf(w.z, p2.x, a0); a0 = fmaf(w.w, p3.x, a0);
            a1 = fmaf(w.x, p0.y, a1); a1 = fmaf(w.y, p1.y, a1);
            a1 = fmaf(w.z, p2.y, a1); a1 = fmaf(w.w, p3.y, a1);
            a2 = fmaf(w.x, p0.z, a2); a2 = fmaf(w.y, p1.z, a2);
            a2 = fmaf(w.z, p2.z, a2); a2 = fmaf(w.w, p3.z, a2);
            a3 = fmaf(w.x, p0.w, a3); a3 = fmaf(w.y, p1.w, a3);
            a3 = fmaf(w.z, p2.w, a3); a3 = fmaf(w.w, p3.w, a3);
        }

        h_s[cur ^ 1][j] = make_float4(tanhf(a0), tanhf(a1), tanhf(a2), tanhf(a3));
        __syncthreads();   // writes done, x_s free to overwrite
        cur ^= 1;
    }

    // epilogue: y[b0+m][o] = by[o] + sum_k Wy[o][k] * h_T[m][k]
    const int m = tid >> 7;          // 0..3
    const int o = tid & 127;         // 0..127
    const float* __restrict__ hflat = reinterpret_cast<const float*>(h_s[cur]);
    const float4* __restrict__ Wy4  = reinterpret_cast<const float4*>(Wy);

    float acc = by[o];
    #pragma unroll 8
    for (int k4 = 0; k4 < HH / 4; ++k4) {
        float4 w = Wy4[o * (HH / 4) + k4];
        acc = fmaf(w.x, hflat[(k4 * 4 + 0) * 4 + m], acc);
        acc = fmaf(w.y, hflat[(k4 * 4 + 1) * 4 + m], acc);
        acc = fmaf(w.z, hflat[(k4 * 4 + 2) * 4 + m], acc);
        acc = fmaf(w.w, hflat[(k4 * 4 + 3) * 4 + m], acc);
    }
    y[(b0 + m) * DOUT + o] = acc;
}

extern "C" void kernel_launch(void* const* d_in, const int* in_sizes, int n_in,
                              void* d_out, int out_size) {
    const float* x  = (const float*)d_in[0];
    const float* Wx = (const float*)d_in[1];
    const float* bx = (const float*)d_in[2];
    const float* Wh = (const float*)d_in[3];
    const float* bh = (const float*)d_in[4];
    const float* Wy = (const float*)d_in[5];
    const float* by = (const float*)d_in[6];
    float* y = (float*)d_out;

    prep_kernel<<<256, 256>>>(Wh, Wx);
    scan_kernel<<<NCTA, NTHR>>>(x, bx, bh, Wy, by, y);
}

// round 3
// speedup vs baseline: 1.0006x; 1.0002x over previous
#include <cuda_runtime.h>
#include <math.h>

#define BB   512
#define TT   1024
#define DIN  128
#define HH   512
#define DOUT 128
#define MB   4
#define NCTA (BB / MB)   // 128
#define NTHR 512

// Scratch: weights re-laid-out as [k/4][j][4] so thread j streams float4
// over K with perfectly coalesced LDG.128 (lanes consecutive j -> 16B stride).
__device__ float g_Wh4[HH * HH];    // 1 MB
__device__ float g_Wx4[DIN * HH];   // 256 KB

__global__ void prep_kernel(const float* __restrict__ Wh,
                            const float* __restrict__ Wx) {
    int i = blockIdx.x * blockDim.x + threadIdx.x;
    int stride = gridDim.x * blockDim.x;
    for (int idx = i; idx < HH * HH; idx += stride) {
        int j = idx / HH;
        int k = idx % HH;
        g_Wh4[(k >> 2) * (HH * 4) + j * 4 + (k & 3)] = Wh[idx];
    }
    for (int idx = i; idx < HH * DIN; idx += stride) {
        int j = idx / DIN;
        int d = idx % DIN;
        g_Wx4[(d >> 2) * (HH * 4) + j * 4 + (d & 3)] = Wx[idx];
    }
}

__global__ __launch_bounds__(NTHR, 1) void scan_kernel(
    const float* __restrict__ x,
    const float* __restrict__ bx,
    const float* __restrict__ bh,
    const float* __restrict__ Wy,
    const float* __restrict__ by,
    float* __restrict__ y)
{
    // h_s[buf][k] : float4 components are the MB=4 batch rows (layout [k][m])
    __shared__ float4 h_s[2][HH];   // 2 x 8 KB
    __shared__ float4 x_s[DIN];     // 2 KB, layout [d][m]

    const int tid = threadIdx.x;
    const int j   = tid;            // this thread owns hidden unit j
    const int b0  = blockIdx.x * MB;

    const float bias = bx[j] + bh[j];

    const float4* __restrict__ Wh4 = reinterpret_cast<const float4*>(g_Wh4);
    const float4* __restrict__ Wx4 = reinterpret_cast<const float4*>(g_Wx4);

    // h_0 = 0
    h_s[0][tid] = make_float4(0.f, 0.f, 0.f, 0.f);

    const int xd = tid >> 2;        // d index for x staging
    const int xm = tid & 3;         // m index for x staging
    const long xbase = ((long)(b0 + xm) * TT) * DIN + xd;

    int cur = 0;
    for (int t = 0; t < TT; ++t) {
        // stage x[b0+m][t][:]  (x_s flat index d*4+m == tid)
        reinterpret_cast<float*>(x_s)[tid] = x[xbase + (long)t * DIN];
        __syncthreads();   // x_s ready; h_s[cur] ready from previous step

        float a0 = bias, a1 = bias, a2 = bias, a3 = bias;

        // input projection: a_m += sum_d Wx[j][d] * x[m][d]
        #pragma unroll 4
        for (int d4 = 0; d4 < DIN / 4; ++d4) {
            float4 w  = Wx4[d4 * HH + j];
            float4 p0 = x_s[d4 * 4 + 0];
            float4 p1 = x_s[d4 * 4 + 1];
            float4 p2 = x_s[d4 * 4 + 2];
            float4 p3 = x_s[d4 * 4 + 3];
            a0 = fmaf(w.x, p0.x, a0); a0 = fmaf(w.y, p1.x, a0);
            a0 = fmaf(w.z, p2.x, a0); a0 = fmaf(w.w, p3.x, a0);
            a1 = fmaf(w.x, p0.y, a1); a1 = fmaf(w.y, p1.y, a1);
            a1 = fmaf(w.z, p2.y, a1); a1 = fmaf(w.w, p3.y, a1);
            a2 = fmaf(w.x, p0.z, a2); a2 = fmaf(w.y, p1.z, a2);
            a2 = fmaf(w.z, p2.z, a2); a2 = fmaf(w.w, p3.z, a2);
            a3 = fmaf(w.x, p0.w, a3); a3 = fmaf(w.y, p1.w, a3);
            a3 = fmaf(w.z, p2.w, a3); a3 = fmaf(w.w, p3.w, a3);
        }

        // recurrence: a_m += sum_k Wh[j][k] * h[m][k]
        const float4* __restrict__ hc = h_s[cur];
        #pragma unroll 8
        for (int k4 = 0; k4 < HH / 4; ++k4) {
            float4 w  = Wh4[k4 * HH + j];
            float4 p0 = hc[k4 * 4 + 0];
            float4 p1 = hc[k4 * 4 + 1];
            float4 p2 = hc[k4 * 4 + 2];
            float4 p3 = hc[k4 * 4 + 3];
            a0 = fmaf(w.x, p0.x, a0); a0 = fmaf(w.y, p1.x, a0);
            a0 = fmaf(w.z, p2.x, a0); a0 = fmaf(w.w, p3.x, a0);
            a1 = fmaf(w.x, p0.y, a1); a1 = fmaf(w.y, p1.y, a1);
            a1 = fmaf(w.z, p2.y, a1); a1 = fmaf(w.w, p3.y, a1);
            a2 = fmaf(w.x, p0.z, a2); a2 = fmaf(w.y, p1.z, a2);
            a2 = fmaf(w.z, p2.z, a2); a2 = fmaf(w.w, p3.z, a2);
            a3 = fmaf(w.x, p0.w, a3); a3 = fmaf(w.y, p1.w, a3);
            a3 = fmaf(w.z, p2.w, a3); a3 = fmaf(w.w, p3.w, a3);
        }

        h_s[cur ^ 1][j] = make_float4(tanhf(a0), tanhf(a1), tanhf(a2), tanhf(a3));
        __syncthreads();   // writes done, x_s free to overwrite
        cur ^= 1;
    }

    // epilogue: y[b0+m][o] = by[o] + sum_k Wy[o][k] * h_T[m][k]
    const int m = tid >> 7;          // 0..3
    const int o = tid & 127;         // 0..127
    const float* __restrict__ hflat = reinterpret_cast<const float*>(h_s[cur]);
    const float4* __restrict__ Wy4  = reinterpret_cast<const float4*>(Wy);

    float acc = by[o];
    #pragma unroll 8
    for (int k4 = 0; k4 < HH / 4; ++k4) {
        float4 w = Wy4[o * (HH / 4) + k4];
        acc = fmaf(w.x, hflat[(k4 * 4 + 0) * 4 + m], acc);
        acc = fmaf(w.y, hflat[(k4 * 4 + 1) * 4 + m], acc);
        acc = fmaf(w.z, hflat[(k4 * 4 + 2) * 4 + m], acc);
        acc = fmaf(w.w, hflat[(k4 * 4 + 3) * 4 + m], acc);
    }
    y[(b0 + m) * DOUT + o] = acc;
}

extern "C" void kernel_launch(void* const* d_in, const int* in_sizes, int n_in,
                              void* d_out, int out_size) {
    const float* x  = (const float*)d_in[0];
    const float* Wx = (const float*)d_in[1];
    const float* bx = (const float*)d_in[2];
    const float* Wh = (const float*)d_in[3];
    const float* bh = (const float*)d_in[4];
    const float* Wy = (const float*)d_in[5];
    const float* by = (const float*)d_in[6];
    float* y = (float*)d_out;

    prep_kernel<<<256, 256>>>(Wh, Wx);
    scan_kernel<<<NCTA, NTHR>>>(x, bx, bh, Wy, by, y);
}

// round 4
// speedup vs baseline: 1.1346x; 1.1340x over previous
#include <cuda_runtime.h>
#include <math.h>
#include <stdint.h>

#define TT   1024
#define BB   512
#define DIN  128
#define HH   512
#define DOUT 128

#define NG   16      // batch groups
#define NS   8       // j slices
#define MB   32      // batch rows per group
#define JS   64      // hidden outputs per slice
#define KT   640     // unified reduction: [0,512)=h, [512,640)=x
#define CHUNK 160
#define NCH  4
#define NTHR 256

#define WP   644     // w_s row pitch (floats): 644*4=2576B, 16B aligned, bank-friendly
#define VP   164     // v_s row pitch (floats): 656B, 16B aligned, +16B bank skew

// Cross-CTA hidden-state exchange buffers (double-buffered by step parity)
__device__ float    g_hbuf[2][BB][HH];   // 2 MB, L2-resident
__device__ unsigned g_cnt[NG * 32];      // per-group barrier counters, 128B apart

__global__ void zero_kernel() {
    int i = blockIdx.x * blockDim.x + threadIdx.x;
    int stride = gridDim.x * blockDim.x;
    float* p = &g_hbuf[0][0][0];
    for (int k = i; k < BB * HH; k += stride) p[k] = 0.f;
    if (i < NG * 32) g_cnt[i] = 0u;
}

__device__ __forceinline__ void lds_v2(uint64_t& a, uint64_t& b, uint32_t addr) {
    asm volatile("ld.shared.v2.u64 {%0,%1}, [%2];" : "=l"(a), "=l"(b) : "r"(addr));
}
#define FMA2(acc, w, h) \
    asm("fma.rn.f32x2 %0, %1, %2, %0;" : "+l"(acc) : "l"(w), "l"(h))

__device__ __forceinline__ float2 unpack2(uint64_t a) {
    float lo, hi;
    asm("mov.b64 {%0,%1}, %2;" : "=f"(lo), "=f"(hi) : "l"(a));
    return make_float2(lo, hi);
}

__global__ __launch_bounds__(NTHR, 1) void scan_kernel(
    const float* __restrict__ x,
    const float* __restrict__ Wx,
    const float* __restrict__ bx,
    const float* __restrict__ Wh,
    const float* __restrict__ bh,
    const float* __restrict__ Wy,
    const float* __restrict__ by,
    float* __restrict__ y)
{
    extern __shared__ float sm[];
    float* w_s = sm;                 // [JS][WP]
    float* v_s = sm + JS * WP;       // [2][MB][VP]

    const int tid = threadIdx.x;
    const int g   = blockIdx.x >> 3;   // batch group
    const int s   = blockIdx.x & 7;    // j slice
    const int jp  = tid >> 3;          // 0..31 : thread's j-pair base (j in {jp, jp+32})
    const int mq  = tid & 7;           // 0..7  : thread's m set {mq, mq+8, mq+16, mq+24}
    const int rr  = tid >> 3;          // reload row
    const int cb  = tid & 7;           // reload col base

    // ---- load unified weight slice into smem (once) ----
    const float4* Wh4 = reinterpret_cast<const float4*>(Wh);
    const float4* Wx4 = reinterpret_cast<const float4*>(Wx);
    for (int i = tid; i < JS * (HH / 4); i += NTHR) {
        int jl = i >> 7, c4 = i & 127;
        float4 w = Wh4[(size_t)(s * JS + jl) * (HH / 4) + c4];
        *reinterpret_cast<float4*>(&w_s[jl * WP + c4 * 4]) = w;
    }
    for (int i = tid; i < JS * (DIN / 4); i += NTHR) {
        int jl = i >> 5, c4 = i & 31;
        float4 w = Wx4[(size_t)(s * JS + jl) * (DIN / 4) + c4];
        *reinterpret_cast<float4*>(&w_s[jl * WP + HH + c4 * 4]) = w;
    }
    const int jg0 = s * JS + jp, jg1 = jg0 + 32;
    const float bias0 = bx[jg0] + bh[jg0];
    const float bias1 = bx[jg1] + bh[jg1];
    __syncthreads();

    const uint32_t w_sh = (uint32_t)__cvta_generic_to_shared(w_s);
    const uint32_t v_sh = (uint32_t)__cvta_generic_to_shared(v_s);
    unsigned* cnt = &g_cnt[g * 32];

    float4 pre[5];
    int p = 0;

    for (int t = 0; t < TT; ++t) {
        uint64_t acc[2][4];
        #pragma unroll
        for (int jj = 0; jj < 2; ++jj)
            #pragma unroll
            for (int i = 0; i < 4; ++i) acc[jj][i] = 0ull;

        // prologue: LDG chunk 0
        {
            const int c = 0;
            #pragma unroll
            for (int q = 0; q < 5; ++q) {
                int k = c * CHUNK + (cb + 8 * q) * 4;
                pre[q] = __ldcg(reinterpret_cast<const float4*>(
                             &g_hbuf[p][g * MB + rr][k]));
            }
        }

        #pragma unroll
        for (int c = 0; c < NCH; ++c) {
            const int vb = c & 1;
            // STS staged chunk
            #pragma unroll
            for (int q = 0; q < 5; ++q) {
                int c4 = cb + 8 * q;
                *reinterpret_cast<float4*>(
                    &v_s[(vb * MB + rr) * VP + c4 * 4]) = pre[q];
            }
            __syncthreads();
            // prefetch next chunk
            if (c + 1 < NCH) {
                const int cn = c + 1;
                #pragma unroll
                for (int q = 0; q < 5; ++q) {
                    int k = cn * CHUNK + (cb + 8 * q) * 4;
                    if (cn < 3 || q == 0) {
                        pre[q] = __ldcg(reinterpret_cast<const float4*>(
                                     &g_hbuf[p][g * MB + rr][k]));
                    } else {
                        pre[q] = __ldg(reinterpret_cast<const float4*>(
                                     &x[(size_t)(g * MB + rr) * TT * DIN
                                        + (size_t)t * DIN + (k - HH)]));
                    }
                }
            }
            // compute this chunk: 40 k-quads
            const uint32_t wa0 = w_sh + (uint32_t)((jp * WP + c * CHUNK) * 4);
            const uint32_t wa1 = w_sh + (uint32_t)(((jp + 32) * WP + c * CHUNK) * 4);
            uint32_t ha[4];
            #pragma unroll
            for (int i = 0; i < 4; ++i)
                ha[i] = v_sh + (uint32_t)((vb * MB + mq + 8 * i) * VP * 4);

            #pragma unroll 4
            for (int q = 0; q < CHUNK / 4; ++q) {
                uint64_t w0l, w0h, w1l, w1h;
                lds_v2(w0l, w0h, wa0 + q * 16);
                lds_v2(w1l, w1h, wa1 + q * 16);
                #pragma unroll
                for (int i = 0; i < 4; ++i) {
                    uint64_t hl, hh;
                    lds_v2(hl, hh, ha[i] + q * 16);
                    FMA2(acc[0][i], w0l, hl);
                    FMA2(acc[0][i], w0h, hh);
                    FMA2(acc[1][i], w1l, hl);
                    FMA2(acc[1][i], w1h, hh);
                }
            }
        }

        // finalize: reduce f32x2 halves, bias, tanh, publish
        const int q2 = p ^ 1;
        #pragma unroll
        for (int jj = 0; jj < 2; ++jj) {
            const float bb = jj ? bias1 : bias0;
            const int   jc = s * JS + jp + 32 * jj;
            #pragma unroll
            for (int i = 0; i < 4; ++i) {
                float2 v = unpack2(acc[jj][i]);
                float hval = tanhf(v.x + v.y + bb);
                g_hbuf[q2][g * MB + mq + 8 * i][jc] = hval;
            }
        }
        __threadfence();
        if (tid == 0) {
            atomicAdd(cnt, 1u);
            const unsigned tgt = (unsigned)(NS * (t + 1));
            unsigned v;
            do {
                asm volatile("ld.acquire.gpu.global.u32 %0, [%1];"
                             : "=r"(v) : "l"(cnt));
                if (v < tgt) __nanosleep(64);
            } while (v < tgt);
        }
        __syncthreads();
        p ^= 1;
    }

    // ---- epilogue: y[b, o] = by[o] + sum_k Wy[o,k] * h_T[b,k]; h_T in g_hbuf[0]
    const int o0 = s * 16 + 2 * cb;          // this thread's o-pair
    const int me = rr;                        // its batch row (local)
    uint64_t ya = 0ull, yb = 0ull;
    const ulonglong2* Wy2 = reinterpret_cast<const ulonglong2*>(Wy);

    #pragma unroll
    for (int c = 0; c < 4; ++c) {
        #pragma unroll
        for (int qq = 0; qq < 4; ++qq) {
            int c4 = cb + 8 * qq;             // 0..31
            float4 vv = __ldcg(reinterpret_cast<const float4*>(
                            &g_hbuf[0][g * MB + rr][c * 128 + c4 * 4]));
            *reinterpret_cast<float4*>(&v_s[rr * VP + c4 * 4]) = vv;
        }
        __syncthreads();
        #pragma unroll 8
        for (int qk = 0; qk < 32; ++qk) {
            uint64_t hl, hh;
            lds_v2(hl, hh, v_sh + (uint32_t)(me * VP * 4) + qk * 16);
            ulonglong2 wA = __ldg(&Wy2[(size_t)o0 * 128 + c * 32 + qk]);
            ulonglong2 wB = __ldg(&Wy2[(size_t)(o0 + 1) * 128 + c * 32 + qk]);
            FMA2(ya, wA.x, hl);
            FMA2(ya, wA.y, hh);
            FMA2(yb, wB.x, hl);
            FMA2(yb, wB.y, hh);
        }
        __syncthreads();
    }
    {
        float2 a = unpack2(ya), b = unpack2(yb);
        y[(size_t)(g * MB + me) * DOUT + o0]     = by[o0]     + a.x + a.y;
        y[(size_t)(g * MB + me) * DOUT + o0 + 1] = by[o0 + 1] + b.x + b.y;
    }
}

extern "C" void kernel_launch(void* const* d_in, const int* in_sizes, int n_in,
                              void* d_out, int out_size) {
    const float* x  = (const float*)d_in[0];
    const float* Wx = (const float*)d_in[1];
    const float* bx = (const float*)d_in[2];
    const float* Wh = (const float*)d_in[3];
    const float* bh = (const float*)d_in[4];
    const float* Wy = (const float*)d_in[5];
    const float* by = (const float*)d_in[6];
    float* y = (float*)d_out;

    const int smem_bytes = (JS * WP + 2 * MB * VP) * (int)sizeof(float); // 206,848 B
    static int attr_set = 0;
    cudaFuncSetAttribute(scan_kernel,
                         cudaFuncAttributeMaxDynamicSharedMemorySize, smem_bytes);
    (void)attr_set;

    zero_kernel<<<256, 256>>>();
    scan_kernel<<<NG * NS, NTHR, smem_bytes>>>(x, Wx, bx, Wh, bh, Wy, by, y);
}